// round 9
// baseline (speedup 1.0000x reference)
#include <cuda_runtime.h>
#include <cuda_bf16.h>
#include <math.h>
#include <stdint.h>

#define T_TOKENS 1024
#define H_DIM    2048
#define I_DIM    1408
#define SI_DIM   5632
#define NE       8

typedef __nv_bfloat16 bf16;
typedef __nv_bfloat162 bf162;

// ---------------------------------------------------------------------------
// Scratch (__device__ globals; no cudaMalloc allowed)
// ---------------------------------------------------------------------------
__device__ int   g_cnt[NE];
__device__ int   g_tok [NE * T_TOKENS];
__device__ int   g_slot[NE * T_TOKENS];
__device__ float g_wt  [NE * T_TOKENS];
__device__ float g_sgate[T_TOKENS];

__device__ bf16 g_hid_hi[(size_t)T_TOKENS * H_DIM];
__device__ bf16 g_hid_lo[(size_t)T_TOKENS * H_DIM];
__device__ bf16 g_wg_hi[(size_t)NE * H_DIM * I_DIM];
__device__ bf16 g_wg_lo[(size_t)NE * H_DIM * I_DIM];
__device__ bf16 g_wu_hi[(size_t)NE * H_DIM * I_DIM];
__device__ bf16 g_wu_lo[(size_t)NE * H_DIM * I_DIM];
__device__ bf16 g_wd_hi[(size_t)NE * I_DIM * H_DIM];
__device__ bf16 g_wd_lo[(size_t)NE * I_DIM * H_DIM];
__device__ bf16 g_swg_hi[(size_t)H_DIM * SI_DIM];
__device__ bf16 g_swg_lo[(size_t)H_DIM * SI_DIM];
__device__ bf16 g_swu_hi[(size_t)H_DIM * SI_DIM];
__device__ bf16 g_swu_lo[(size_t)H_DIM * SI_DIM];
__device__ bf16 g_swd_hi[(size_t)SI_DIM * H_DIM];
__device__ bf16 g_swd_lo[(size_t)SI_DIM * H_DIM];

__device__ bf16  g_act_hi[(size_t)NE * T_TOKENS * I_DIM];
__device__ bf16  g_act_lo[(size_t)NE * T_TOKENS * I_DIM];
__device__ bf16  g_shact_hi[(size_t)T_TOKENS * SI_DIM];
__device__ bf16  g_shact_lo[(size_t)T_TOKENS * SI_DIM];
__device__ float g_contrib[(size_t)T_TOKENS * 2 * H_DIM];

// ---------------------------------------------------------------------------
__global__ void zero_cnt_kernel() {
    if (threadIdx.x < NE) g_cnt[threadIdx.x] = 0;
}

__global__ __launch_bounds__(256) void router_kernel(
    const float* __restrict__ hidden,
    const float* __restrict__ gate_w,
    const float* __restrict__ shared_gate_w,
    float* __restrict__ out_logits)
{
    const int t = blockIdx.x;
    __shared__ float sh[H_DIM];
    __shared__ float slog[NE];
    __shared__ float sred[256];

    const float* hrow = hidden + (size_t)t * H_DIM;
    for (int i = threadIdx.x; i < H_DIM; i += 256) sh[i] = hrow[i];
    __syncthreads();

    const int warp = threadIdx.x >> 5;
    const int lane = threadIdx.x & 31;

    float sum = 0.f;
    for (int k = lane; k < H_DIM; k += 32) sum += sh[k] * gate_w[k * NE + warp];
    #pragma unroll
    for (int o = 16; o; o >>= 1) sum += __shfl_down_sync(0xffffffffu, sum, o);
    if (lane == 0) slog[warp] = sum;

    float s2 = 0.f;
    for (int k = threadIdx.x; k < H_DIM; k += 256) s2 += sh[k] * shared_gate_w[k];
    sred[threadIdx.x] = s2;
    __syncthreads();
    for (int st = 128; st; st >>= 1) {
        if (threadIdx.x < st) sred[threadIdx.x] += sred[threadIdx.x + st];
        __syncthreads();
    }

    if (threadIdx.x == 0) {
        float lg[NE];
        float mx = -1e30f;
        #pragma unroll
        for (int e = 0; e < NE; ++e) { lg[e] = slog[e]; mx = fmaxf(mx, lg[e]); }
        float p[NE]; float den = 0.f;
        #pragma unroll
        for (int e = 0; e < NE; ++e) { p[e] = expf(lg[e] - mx); den += p[e]; }
        float inv = 1.f / den;
        #pragma unroll
        for (int e = 0; e < NE; ++e) {
            p[e] *= inv;
            out_logits[(size_t)t * NE + e] = lg[e];
        }
        int i0 = 0;
        #pragma unroll
        for (int e = 1; e < NE; ++e) if (p[e] > p[i0]) i0 = e;
        int i1 = -1;
        #pragma unroll
        for (int e = 0; e < NE; ++e) {
            if (e == i0) continue;
            if (i1 < 0 || p[e] > p[i1]) i1 = e;
        }
        int pos0 = atomicAdd(&g_cnt[i0], 1);
        g_tok [i0 * T_TOKENS + pos0] = t;
        g_slot[i0 * T_TOKENS + pos0] = 0;
        g_wt  [i0 * T_TOKENS + pos0] = p[i0];
        int pos1 = atomicAdd(&g_cnt[i1], 1);
        g_tok [i1 * T_TOKENS + pos1] = t;
        g_slot[i1 * T_TOKENS + pos1] = 1;
        g_wt  [i1 * T_TOKENS + pos1] = p[i1];

        g_sgate[t] = 1.f / (1.f + expf(-sred[0]));
    }
}

// ---------------------------------------------------------------------------
// fp32 -> bf16 hi/lo split (memory-bound)
// ---------------------------------------------------------------------------
__global__ __launch_bounds__(256) void split_kernel(
    const float* __restrict__ src, bf16* __restrict__ hi, bf16* __restrict__ lo, int n4)
{
    for (int i = blockIdx.x * 256 + threadIdx.x; i < n4; i += gridDim.x * 256) {
        float4 v = ((const float4*)src)[i];
        bf16 hx = __float2bfloat16_rn(v.x);
        bf16 hy = __float2bfloat16_rn(v.y);
        bf16 hz = __float2bfloat16_rn(v.z);
        bf16 hw = __float2bfloat16_rn(v.w);
        bf16 lx = __float2bfloat16_rn(v.x - __bfloat162float(hx));
        bf16 ly = __float2bfloat16_rn(v.y - __bfloat162float(hy));
        bf16 lz = __float2bfloat16_rn(v.z - __bfloat162float(hz));
        bf16 lw = __float2bfloat16_rn(v.w - __bfloat162float(hw));
        ((bf162*)hi)[2 * i]     = bf162(hx, hy);
        ((bf162*)hi)[2 * i + 1] = bf162(hz, hw);
        ((bf162*)lo)[2 * i]     = bf162(lx, ly);
        ((bf162*)lo)[2 * i + 1] = bf162(lz, lw);
    }
}

// ---------------------------------------------------------------------------
// helpers
// ---------------------------------------------------------------------------
__device__ __forceinline__ uint32_t smem_u32(const void* p) {
    return (uint32_t)__cvta_generic_to_shared(p);
}
__device__ __forceinline__ void ldsm_x4(uint32_t* r, uint32_t a) {
    asm volatile("ldmatrix.sync.aligned.m8n8.x4.shared.b16 {%0,%1,%2,%3}, [%4];"
                 : "=r"(r[0]), "=r"(r[1]), "=r"(r[2]), "=r"(r[3]) : "r"(a));
}
__device__ __forceinline__ void ldsm_x4_t(uint32_t* r, uint32_t a) {
    asm volatile("ldmatrix.sync.aligned.m8n8.x4.trans.shared.b16 {%0,%1,%2,%3}, [%4];"
                 : "=r"(r[0]), "=r"(r[1]), "=r"(r[2]), "=r"(r[3]) : "r"(a));
}
__device__ __forceinline__ void mma16816(float* d, const uint32_t* a, uint32_t b0, uint32_t b1) {
    asm volatile("mma.sync.aligned.m16n8k16.row.col.f32.bf16.bf16.f32 "
                 "{%0,%1,%2,%3}, {%4,%5,%6,%7}, {%8,%9}, {%0,%1,%2,%3};"
                 : "+f"(d[0]), "+f"(d[1]), "+f"(d[2]), "+f"(d[3])
                 : "r"(a[0]), "r"(a[1]), "r"(a[2]), "r"(a[3]), "r"(b0), "r"(b1));
}
__device__ __forceinline__ void split2(float a, float b, uint32_t& hi, uint32_t& lo) {
    bf16 h0 = __float2bfloat16_rn(a), h1 = __float2bfloat16_rn(b);
    bf162 H(h0, h1);
    bf162 L(__float2bfloat16_rn(a - __bfloat162float(h0)),
            __float2bfloat16_rn(b - __bfloat162float(h1)));
    hi = *reinterpret_cast<uint32_t*>(&H);
    lo = *reinterpret_cast<uint32_t*>(&L);
}

#define CP16(dst, src) \
    asm volatile("cp.async.cg.shared.global [%0], [%1], 16;" :: "r"(dst), "l"(src) : "memory")
#define CP_COMMIT() asm volatile("cp.async.commit_group;" ::: "memory")
#define CP_WAIT(n)  asm volatile("cp.async.wait_group %0;" :: "n"(n) : "memory")

// ---------------------------------------------------------------------------
// bf16 hi/lo 3-term GEMM via mma.sync + cp.async double buffering.
// CTA tile M=128 x N=128, 256 threads = 8 warps (4m x 2n), warp tile 32x64.
// A [rows, K] bf16 hi/lo (K-major). B [K, Ntot] bf16 hi/lo.
// DUAL=1: N=128 tile is [gate(64) | up(64)], both at column n0 of their matrix;
//         grid.x step 64. Epilogue: silu(gate)*up -> bf16 hi/lo at cols n0..n0+63.
// DUAL=0: plain 128-wide tile of B0; grid.x step 128.
// EPI: 0 = gateup combine; 1 = expert scatter x routing weight; 2 = shared combine.
//
// SMEM stage layout (byte offsets within stage):
//   AHI [128][40]bf16 @ 0      (10240 B, row stride 80)
//   ALO                @ 10240
//   BHI [32][136]bf16  @ 20480 (8704 B, row stride 272)
//   BLO                @ 29184
//   stage size 37888, двух stages.
// ---------------------------------------------------------------------------
#define ASTRIDE 80
#define BSTRIDE 272
#define AHI_OFF 0
#define ALO_OFF 10240
#define BHI_OFF 20480
#define BLO_OFF 29184
#define STAGE   37888
#define SMEM_DYN (2 * STAGE)

template<int GATHER, int AEXP, int DUAL, int EPI>
__global__ void __launch_bounds__(256, 2) mma2_gemm(
    const bf16* __restrict__ Ahi, const bf16* __restrict__ Alo,
    const bf16* __restrict__ B0hi, const bf16* __restrict__ B0lo,
    const bf16* __restrict__ B1hi, const bf16* __restrict__ B1lo,
    bf16* __restrict__ outHi, bf16* __restrict__ outLo,
    float* __restrict__ outF, int K, int Ntot)
{
    const int e  = blockIdx.z;
    const int m0 = blockIdx.y * 128;
    const int n0 = blockIdx.x * (DUAL ? 64 : 128);
    const int cnt = (GATHER || AEXP) ? g_cnt[e] : T_TOKENS;
    if (m0 >= cnt) return;

    extern __shared__ char db[];
    __shared__ int s_tok[128];

    const int tid  = threadIdx.x;
    const int lane = tid & 31;
    const int warp = tid >> 5;
    const int wm = warp & 3;      // 4 m-warps (32 rows each)
    const int wn = warp >> 2;     // 2 n-warps (64 cols each)

    if (GATHER && tid < 128) {
        int gm = m0 + tid;
        s_tok[tid] = (gm < cnt) ? g_tok[e * T_TOKENS + gm] : 0;
    }
    __syncthreads();

    // ---- A loader: thread -> row tid>>1, 16 k elems at (tid&1)*16 ----
    const int arow_l = tid >> 1;
    const int akoff  = (tid & 1) * 16;
    size_t arow;
    if (GATHER) arow = (size_t)s_tok[arow_l];
    else        arow = (AEXP ? (size_t)e * T_TOKENS : 0) + m0 + arow_l;
    const bf16* aHiP = Ahi + arow * K + akoff;
    const bf16* aLoP = Alo + arow * K + akoff;
    const uint32_t aDst = smem_u32(db) + (uint32_t)(arow_l * ASTRIDE + (tid & 1) * 32);

    // ---- B loader: thread -> k-row tid>>3, 16 n elems at ((tid&7)*2)*8 ----
    const int bkr  = tid >> 3;
    const int bseg = (tid & 7) * 2;          // chunk pair start (16B chunks)
    const int segcol = bseg * 8;             // 0..120 within 128-wide tile
    const size_t eoff = (GATHER || AEXP) ? (size_t)e * K * Ntot : 0;
    const bf16* bHiSrc; const bf16* bLoSrc; int gcol;
    if (DUAL) {
        if (segcol < 64) { bHiSrc = B0hi; bLoSrc = B0lo; gcol = n0 + segcol; }
        else             { bHiSrc = B1hi; bLoSrc = B1lo; gcol = n0 + segcol - 64; }
    } else {
        bHiSrc = B0hi; bLoSrc = B0lo; gcol = n0 + segcol;
    }
    const bf16* bHiP = bHiSrc + eoff + (size_t)bkr * Ntot + gcol;
    const bf16* bLoP = bLoSrc + eoff + (size_t)bkr * Ntot + gcol;
    const uint32_t bDst = smem_u32(db) + (uint32_t)(BHI_OFF + bkr * BSTRIDE + segcol * 2);

    auto issue_stage = [&](int k0, int s) {
        const uint32_t so = (uint32_t)(s * STAGE);
        CP16(aDst + so,      aHiP + k0);
        CP16(aDst + so + 16, aHiP + k0 + 8);
        CP16(aDst + so + (ALO_OFF - AHI_OFF),      aLoP + k0);
        CP16(aDst + so + (ALO_OFF - AHI_OFF) + 16, aLoP + k0 + 8);
        const bf16* bh = bHiP + (size_t)k0 * Ntot;
        const bf16* bl = bLoP + (size_t)k0 * Ntot;
        CP16(bDst + so,      bh);
        CP16(bDst + so + 16, bh + 8);
        CP16(bDst + so + (BLO_OFF - BHI_OFF),      bl);
        CP16(bDst + so + (BLO_OFF - BHI_OFF) + 16, bl + 8);
    };

    float acc[2][8][4];
    #pragma unroll
    for (int i = 0; i < 2; ++i)
        #pragma unroll
        for (int j = 0; j < 8; ++j)
            #pragma unroll
            for (int v = 0; v < 4; ++v) acc[i][j][v] = 0.f;

    const int grp = lane >> 3;
    const int gl  = lane & 7;
    const int a_row_off = (grp & 1) * 8 + gl;
    const int a_col_off = (grp >> 1) * 8;
    const int b_row_off = (grp & 1) * 8 + gl;
    const int b_col_off = (grp >> 1) * 8;

    const int C = K / 32;
    issue_stage(0, 0);
    CP_COMMIT();

    for (int c = 0; c < C; ++c) {
        if (c + 1 < C) {
            issue_stage((c + 1) * 32, (c + 1) & 1);
            CP_COMMIT();
            CP_WAIT(1);
        } else {
            CP_WAIT(0);
        }
        __syncthreads();

        const uint32_t base = smem_u32(db) + (uint32_t)((c & 1) * STAGE);
        #pragma unroll
        for (int ks = 0; ks < 32; ks += 16) {
            uint32_t ah[2][4], al[2][4];
            #pragma unroll
            for (int mi = 0; mi < 2; ++mi) {
                const uint32_t ra = base + (uint32_t)((wm * 32 + mi * 16 + a_row_off) * ASTRIDE + (ks + a_col_off) * 2);
                ldsm_x4(ah[mi], ra);
                ldsm_x4(al[mi], ra + (ALO_OFF - AHI_OFF));
            }
            #pragma unroll
            for (int g = 0; g < 4; ++g) {
                uint32_t bh[4], bl[4];
                const uint32_t rb = base + (uint32_t)(BHI_OFF + (ks + b_row_off) * BSTRIDE + (wn * 64 + g * 16 + b_col_off) * 2);
                ldsm_x4_t(bh, rb);
                ldsm_x4_t(bl, rb + (BLO_OFF - BHI_OFF));
                #pragma unroll
                for (int mi = 0; mi < 2; ++mi) {
                    #pragma unroll
                    for (int half = 0; half < 2; ++half) {
                        const int nj = g * 2 + half;
                        const int p = half * 2;
                        mma16816(acc[mi][nj], ah[mi], bh[p], bh[p + 1]);
                        mma16816(acc[mi][nj], ah[mi], bl[p], bl[p + 1]);
                        mma16816(acc[mi][nj], al[mi], bh[p], bh[p + 1]);
                    }
                }
            }
        }
        __syncthreads();
    }

    // ---- epilogues ----
    if (EPI == 0) {
        // gate = wn 0 cols (local 0..63), up = wn 1 cols. Exchange up accs.
        float* exch = (float*)db;   // [128][72]
        if (wn == 1) {
            #pragma unroll
            for (int mi = 0; mi < 2; ++mi)
                #pragma unroll
                for (int nj = 0; nj < 8; ++nj) {
                    const int cl = nj * 8 + (lane & 3) * 2;
                    #pragma unroll
                    for (int h = 0; h < 2; ++h) {
                        const int rl = wm * 32 + mi * 16 + (lane >> 2) + h * 8;
                        exch[rl * 72 + cl]     = acc[mi][nj][h * 2];
                        exch[rl * 72 + cl + 1] = acc[mi][nj][h * 2 + 1];
                    }
                }
        }
        __syncthreads();
        if (wn == 0) {
            #pragma unroll
            for (int mi = 0; mi < 2; ++mi)
                #pragma unroll
                for (int h = 0; h < 2; ++h) {
                    const int rl = wm * 32 + mi * 16 + (lane >> 2) + h * 8;
                    const int r = m0 + rl;
                    if (GATHER && r >= cnt) continue;
                    const size_t row = (GATHER ? (size_t)e * T_TOKENS : 0) + r;
                    #pragma unroll
                    for (int nj = 0; nj < 8; ++nj) {
                        const int cl = nj * 8 + (lane & 3) * 2;
                        const float g0 = acc[mi][nj][h * 2];
                        const float g1 = acc[mi][nj][h * 2 + 1];
                        const float u0 = exch[rl * 72 + cl];
                        const float u1 = exch[rl * 72 + cl + 1];
                        const float a0 = (g0 / (1.f + expf(-g0))) * u0;
                        const float a1 = (g1 / (1.f + expf(-g1))) * u1;
                        uint32_t hi, lo; split2(a0, a1, hi, lo);
                        *(uint32_t*)(outHi + row * Ntot + n0 + cl) = hi;
                        *(uint32_t*)(outLo + row * Ntot + n0 + cl) = lo;
                    }
                }
        }
    } else {
        #pragma unroll
        for (int mi = 0; mi < 2; ++mi)
            #pragma unroll
            for (int h = 0; h < 2; ++h) {
                const int rl = wm * 32 + mi * 16 + (lane >> 2) + h * 8;
                const int r = m0 + rl;
                if (EPI == 1) {
                    if (r >= cnt) continue;
                    const int idx = e * T_TOKENS + r;
                    const float w = g_wt[idx];
                    float* orow = g_contrib + ((size_t)g_tok[idx] * 2 + g_slot[idx]) * H_DIM;
                    #pragma unroll
                    for (int nj = 0; nj < 8; ++nj) {
                        const int c = n0 + wn * 64 + nj * 8 + (lane & 3) * 2;
                        float2 o = {acc[mi][nj][h * 2] * w, acc[mi][nj][h * 2 + 1] * w};
                        *(float2*)(orow + c) = o;
                    }
                } else {
                    const float sg = g_sgate[r];
                    #pragma unroll
                    for (int nj = 0; nj < 8; ++nj) {
                        const int c = n0 + wn * 64 + nj * 8 + (lane & 3) * 2;
                        const float2 c0 = *(const float2*)(g_contrib + ((size_t)r * 2 + 0) * H_DIM + c);
                        const float2 c1 = *(const float2*)(g_contrib + ((size_t)r * 2 + 1) * H_DIM + c);
                        float2 o = {sg * acc[mi][nj][h * 2] + c0.x + c1.x,
                                    sg * acc[mi][nj][h * 2 + 1] + c0.y + c1.y};
                        *(float2*)(outF + (size_t)r * H_DIM + c) = o;
                    }
                }
            }
    }
}

// ---------------------------------------------------------------------------
extern "C" void kernel_launch(void* const* d_in, const int* in_sizes, int n_in,
                              void* d_out, int out_size)
{
    const float* hidden        = (const float*)d_in[0];
    const float* gate_w        = (const float*)d_in[1];
    const float* w_gate        = (const float*)d_in[2];
    const float* w_up          = (const float*)d_in[3];
    const float* w_down        = (const float*)d_in[4];
    const float* sw_gate       = (const float*)d_in[5];
    const float* sw_up         = (const float*)d_in[6];
    const float* sw_down       = (const float*)d_in[7];
    const float* shared_gate_w = (const float*)d_in[8];

    float* out        = (float*)d_out;
    float* out_logits = out + (size_t)T_TOKENS * H_DIM;

    bf16 *hidHi, *hidLo, *wgHi, *wgLo, *wuHi, *wuLo, *wdHi, *wdLo;
    bf16 *swgHi, *swgLo, *swuHi, *swuLo, *swdHi, *swdLo;
    bf16 *actHi, *actLo, *shHi, *shLo;
    cudaGetSymbolAddress((void**)&hidHi, g_hid_hi);  cudaGetSymbolAddress((void**)&hidLo, g_hid_lo);
    cudaGetSymbolAddress((void**)&wgHi, g_wg_hi);    cudaGetSymbolAddress((void**)&wgLo, g_wg_lo);
    cudaGetSymbolAddress((void**)&wuHi, g_wu_hi);    cudaGetSymbolAddress((void**)&wuLo, g_wu_lo);
    cudaGetSymbolAddress((void**)&wdHi, g_wd_hi);    cudaGetSymbolAddress((void**)&wdLo, g_wd_lo);
    cudaGetSymbolAddress((void**)&swgHi, g_swg_hi);  cudaGetSymbolAddress((void**)&swgLo, g_swg_lo);
    cudaGetSymbolAddress((void**)&swuHi, g_swu_hi);  cudaGetSymbolAddress((void**)&swuLo, g_swu_lo);
    cudaGetSymbolAddress((void**)&swdHi, g_swd_hi);  cudaGetSymbolAddress((void**)&swdLo, g_swd_lo);
    cudaGetSymbolAddress((void**)&actHi, g_act_hi);  cudaGetSymbolAddress((void**)&actLo, g_act_lo);
    cudaGetSymbolAddress((void**)&shHi, g_shact_hi); cudaGetSymbolAddress((void**)&shLo, g_shact_lo);

    cudaFuncSetAttribute(mma2_gemm<1,0,1,0>, cudaFuncAttributeMaxDynamicSharedMemorySize, SMEM_DYN);
    cudaFuncSetAttribute(mma2_gemm<0,1,0,1>, cudaFuncAttributeMaxDynamicSharedMemorySize, SMEM_DYN);
    cudaFuncSetAttribute(mma2_gemm<0,0,1,0>, cudaFuncAttributeMaxDynamicSharedMemorySize, SMEM_DYN);
    cudaFuncSetAttribute(mma2_gemm<0,0,0,2>, cudaFuncAttributeMaxDynamicSharedMemorySize, SMEM_DYN);

    auto split = [&](const float* s, bf16* h, bf16* l, size_t n) {
        int n4 = (int)(n / 4);
        int grid = (n4 + 255) / 256; if (grid > 4096) grid = 4096;
        split_kernel<<<grid, 256>>>(s, h, l, n4);
    };
    split(hidden,  hidHi, hidLo, (size_t)T_TOKENS * H_DIM);
    split(w_gate,  wgHi,  wgLo,  (size_t)NE * H_DIM * I_DIM);
    split(w_up,    wuHi,  wuLo,  (size_t)NE * H_DIM * I_DIM);
    split(w_down,  wdHi,  wdLo,  (size_t)NE * I_DIM * H_DIM);
    split(sw_gate, swgHi, swgLo, (size_t)H_DIM * SI_DIM);
    split(sw_up,   swuHi, swuLo, (size_t)H_DIM * SI_DIM);
    split(sw_down, swdHi, swdLo, (size_t)SI_DIM * H_DIM);

    zero_cnt_kernel<<<1, 32>>>();
    router_kernel<<<T_TOKENS, 256>>>(hidden, gate_w, shared_gate_w, out_logits);

    // expert gate+up -> act hi/lo
    mma2_gemm<1,0,1,0><<<dim3(I_DIM / 64, T_TOKENS / 128, NE), 256, SMEM_DYN>>>(
        hidHi, hidLo, wgHi, wgLo, wuHi, wuLo, actHi, actLo, nullptr, H_DIM, I_DIM);
    // expert down -> contrib scatter
    mma2_gemm<0,1,0,1><<<dim3(H_DIM / 128, T_TOKENS / 128, NE), 256, SMEM_DYN>>>(
        actHi, actLo, wdHi, wdLo, wdHi, wdLo, nullptr, nullptr, nullptr, I_DIM, H_DIM);
    // shared gate+up -> shact hi/lo
    mma2_gemm<0,0,1,0><<<dim3(SI_DIM / 64, T_TOKENS / 128, 1), 256, SMEM_DYN>>>(
        hidHi, hidLo, swgHi, swgLo, swuHi, swuLo, shHi, shLo, nullptr, H_DIM, SI_DIM);
    // shared down + combine -> out
    mma2_gemm<0,0,0,2><<<dim3(H_DIM / 128, T_TOKENS / 128, 1), 256, SMEM_DYN>>>(
        shHi, shLo, swdHi, swdLo, swdHi, swdLo, nullptr, nullptr, out, SI_DIM, H_DIM);
}

// round 10
// speedup vs baseline: 1.1257x; 1.1257x over previous
#include <cuda_runtime.h>
#include <cuda_bf16.h>
#include <math.h>
#include <stdint.h>

#define T_TOKENS 1024
#define H_DIM    2048
#define I_DIM    1408
#define SI_DIM   5632
#define NE       8

typedef __nv_bfloat16 bf16;
typedef __nv_bfloat162 bf162;

// ---------------------------------------------------------------------------
// Scratch (__device__ globals; no cudaMalloc allowed)
// ---------------------------------------------------------------------------
__device__ int   g_cnt[NE];
__device__ int   g_tok [NE * T_TOKENS];
__device__ int   g_slot[NE * T_TOKENS];
__device__ float g_wt  [NE * T_TOKENS];
__device__ float g_sgate[T_TOKENS];

__device__ bf16 g_hid_hi[(size_t)T_TOKENS * H_DIM];
__device__ bf16 g_hid_lo[(size_t)T_TOKENS * H_DIM];

__device__ bf16  g_act_hi[(size_t)NE * T_TOKENS * I_DIM];
__device__ bf16  g_act_lo[(size_t)NE * T_TOKENS * I_DIM];
__device__ bf16  g_shact_hi[(size_t)T_TOKENS * SI_DIM];
__device__ bf16  g_shact_lo[(size_t)T_TOKENS * SI_DIM];
__device__ float g_contrib[(size_t)T_TOKENS * 2 * H_DIM];

// ---------------------------------------------------------------------------
__global__ void zero_cnt_kernel() {
    if (threadIdx.x < NE) g_cnt[threadIdx.x] = 0;
}

__global__ __launch_bounds__(256) void router_kernel(
    const float* __restrict__ hidden,
    const float* __restrict__ gate_w,
    const float* __restrict__ shared_gate_w,
    float* __restrict__ out_logits)
{
    const int t = blockIdx.x;
    __shared__ float sh[H_DIM];
    __shared__ float slog[NE];
    __shared__ float sred[256];

    const float* hrow = hidden + (size_t)t * H_DIM;
    for (int i = threadIdx.x; i < H_DIM; i += 256) sh[i] = hrow[i];
    __syncthreads();

    const int warp = threadIdx.x >> 5;
    const int lane = threadIdx.x & 31;

    float sum = 0.f;
    for (int k = lane; k < H_DIM; k += 32) sum += sh[k] * gate_w[k * NE + warp];
    #pragma unroll
    for (int o = 16; o; o >>= 1) sum += __shfl_down_sync(0xffffffffu, sum, o);
    if (lane == 0) slog[warp] = sum;

    float s2 = 0.f;
    for (int k = threadIdx.x; k < H_DIM; k += 256) s2 += sh[k] * shared_gate_w[k];
    sred[threadIdx.x] = s2;
    __syncthreads();
    for (int st = 128; st; st >>= 1) {
        if (threadIdx.x < st) sred[threadIdx.x] += sred[threadIdx.x + st];
        __syncthreads();
    }

    if (threadIdx.x == 0) {
        float lg[NE];
        float mx = -1e30f;
        #pragma unroll
        for (int e = 0; e < NE; ++e) { lg[e] = slog[e]; mx = fmaxf(mx, lg[e]); }
        float p[NE]; float den = 0.f;
        #pragma unroll
        for (int e = 0; e < NE; ++e) { p[e] = expf(lg[e] - mx); den += p[e]; }
        float inv = 1.f / den;
        #pragma unroll
        for (int e = 0; e < NE; ++e) {
            p[e] *= inv;
            out_logits[(size_t)t * NE + e] = lg[e];
        }
        int i0 = 0;
        #pragma unroll
        for (int e = 1; e < NE; ++e) if (p[e] > p[i0]) i0 = e;
        int i1 = -1;
        #pragma unroll
        for (int e = 0; e < NE; ++e) {
            if (e == i0) continue;
            if (i1 < 0 || p[e] > p[i1]) i1 = e;
        }
        int pos0 = atomicAdd(&g_cnt[i0], 1);
        g_tok [i0 * T_TOKENS + pos0] = t;
        g_slot[i0 * T_TOKENS + pos0] = 0;
        g_wt  [i0 * T_TOKENS + pos0] = p[i0];
        int pos1 = atomicAdd(&g_cnt[i1], 1);
        g_tok [i1 * T_TOKENS + pos1] = t;
        g_slot[i1 * T_TOKENS + pos1] = 1;
        g_wt  [i1 * T_TOKENS + pos1] = p[i1];

        g_sgate[t] = 1.f / (1.f + expf(-sred[0]));
    }
}

// ---------------------------------------------------------------------------
// fp32 -> bf16 hi/lo split (used ONLY for hidden: 8MB, ~4us)
// ---------------------------------------------------------------------------
__global__ __launch_bounds__(256) void split_kernel(
    const float* __restrict__ src, bf16* __restrict__ hi, bf16* __restrict__ lo, int n4)
{
    for (int i = blockIdx.x * 256 + threadIdx.x; i < n4; i += gridDim.x * 256) {
        float4 v = ((const float4*)src)[i];
        bf16 hx = __float2bfloat16_rn(v.x);
        bf16 hy = __float2bfloat16_rn(v.y);
        bf16 hz = __float2bfloat16_rn(v.z);
        bf16 hw = __float2bfloat16_rn(v.w);
        bf16 lx = __float2bfloat16_rn(v.x - __bfloat162float(hx));
        bf16 ly = __float2bfloat16_rn(v.y - __bfloat162float(hy));
        bf16 lz = __float2bfloat16_rn(v.z - __bfloat162float(hz));
        bf16 lw = __float2bfloat16_rn(v.w - __bfloat162float(hw));
        ((bf162*)hi)[2 * i]     = bf162(hx, hy);
        ((bf162*)hi)[2 * i + 1] = bf162(hz, hw);
        ((bf162*)lo)[2 * i]     = bf162(lx, ly);
        ((bf162*)lo)[2 * i + 1] = bf162(lz, lw);
    }
}

// ---------------------------------------------------------------------------
// helpers
// ---------------------------------------------------------------------------
__device__ __forceinline__ uint32_t smem_u32(const void* p) {
    return (uint32_t)__cvta_generic_to_shared(p);
}
__device__ __forceinline__ void ldsm_x4(uint32_t* r, uint32_t a) {
    asm volatile("ldmatrix.sync.aligned.m8n8.x4.shared.b16 {%0,%1,%2,%3}, [%4];"
                 : "=r"(r[0]), "=r"(r[1]), "=r"(r[2]), "=r"(r[3]) : "r"(a));
}
__device__ __forceinline__ void ldsm_x4_t(uint32_t* r, uint32_t a) {
    asm volatile("ldmatrix.sync.aligned.m8n8.x4.trans.shared.b16 {%0,%1,%2,%3}, [%4];"
                 : "=r"(r[0]), "=r"(r[1]), "=r"(r[2]), "=r"(r[3]) : "r"(a));
}
__device__ __forceinline__ void mma16816(float* d, const uint32_t* a, uint32_t b0, uint32_t b1) {
    asm volatile("mma.sync.aligned.m16n8k16.row.col.f32.bf16.bf16.f32 "
                 "{%0,%1,%2,%3}, {%4,%5,%6,%7}, {%8,%9}, {%0,%1,%2,%3};"
                 : "+f"(d[0]), "+f"(d[1]), "+f"(d[2]), "+f"(d[3])
                 : "r"(a[0]), "r"(a[1]), "r"(a[2]), "r"(a[3]), "r"(b0), "r"(b1));
}
__device__ __forceinline__ void split4(const float4& v, uint2& hi, uint2& lo) {
    bf16 h0 = __float2bfloat16_rn(v.x), h1 = __float2bfloat16_rn(v.y);
    bf16 h2 = __float2bfloat16_rn(v.z), h3 = __float2bfloat16_rn(v.w);
    bf162 H0(h0, h1), H1(h2, h3);
    bf162 L0(__float2bfloat16_rn(v.x - __bfloat162float(h0)),
             __float2bfloat16_rn(v.y - __bfloat162float(h1)));
    bf162 L1(__float2bfloat16_rn(v.z - __bfloat162float(h2)),
             __float2bfloat16_rn(v.w - __bfloat162float(h3)));
    hi.x = *reinterpret_cast<uint32_t*>(&H0); hi.y = *reinterpret_cast<uint32_t*>(&H1);
    lo.x = *reinterpret_cast<uint32_t*>(&L0); lo.y = *reinterpret_cast<uint32_t*>(&L1);
}
__device__ __forceinline__ void split2(float a, float b, uint32_t& hi, uint32_t& lo) {
    bf16 h0 = __float2bfloat16_rn(a), h1 = __float2bfloat16_rn(b);
    bf162 H(h0, h1);
    bf162 L(__float2bfloat16_rn(a - __bfloat162float(h0)),
            __float2bfloat16_rn(b - __bfloat162float(h1)));
    hi = *reinterpret_cast<uint32_t*>(&H);
    lo = *reinterpret_cast<uint32_t*>(&L);
}

#define CP16(dst, src) \
    asm volatile("cp.async.cg.shared.global [%0], [%1], 16;" :: "r"(dst), "l"(src) : "memory")
#define CP_COMMIT() asm volatile("cp.async.commit_group;" ::: "memory")
#define CP_WAIT(n)  asm volatile("cp.async.wait_group %0;" :: "n"(n) : "memory")

// ---------------------------------------------------------------------------
// bf16 hi/lo 3-term GEMM. A bf16 hi/lo via cp.async (double buffer).
// B fp32 from gmem, register-staged split -> smem bf16 hi/lo.
// CTA tile M=128 x N=128, 256 threads = 8 warps (4m x 2n), warp tile 32x64.
// DUAL=1: N tile = [gate(64)|up(64)] at col n0 of each matrix; grid.x step 64.
// EPI: 0 = silu(gate)*up -> bf16 hi/lo; 1 = expert scatter x weight;
//      2 = shared combine (sigmoid gate + contrib -> outF).
// ---------------------------------------------------------------------------
#define ASTRIDE 80
#define BSTRIDE 272
#define ALO_OFF 10240
#define BHI_OFF 20480
#define BLO_OFF 29184
#define STAGE   37888
#define SMEM_DYN (2 * STAGE)

template<int GATHER, int AEXP, int DUAL, int EPI>
__global__ void __launch_bounds__(256, 2) mma2_gemm(
    const bf16* __restrict__ Ahi, const bf16* __restrict__ Alo,
    const float* __restrict__ B0, const float* __restrict__ B1,
    bf16* __restrict__ outHi, bf16* __restrict__ outLo,
    float* __restrict__ outF, int K, int Ntot)
{
    const int e  = blockIdx.z;
    const int m0 = blockIdx.y * 128;
    const int n0 = blockIdx.x * (DUAL ? 64 : 128);
    const int cnt = (GATHER || AEXP) ? g_cnt[e] : T_TOKENS;
    if (m0 >= cnt) return;

    extern __shared__ char db[];
    __shared__ int s_tok[128];

    const int tid  = threadIdx.x;
    const int lane = tid & 31;
    const int warp = tid >> 5;
    const int wm = warp & 3;
    const int wn = warp >> 2;

    if (GATHER && tid < 128) {
        int gm = m0 + tid;
        s_tok[tid] = (gm < cnt) ? g_tok[e * T_TOKENS + gm] : 0;
    }
    __syncthreads();

    // ---- A loader (cp.async): thread -> row tid>>1, 16 k elems at (tid&1)*16 ----
    const int arow_l = tid >> 1;
    size_t arow;
    if (GATHER) arow = (size_t)s_tok[arow_l];
    else        arow = (AEXP ? (size_t)e * T_TOKENS : 0) + m0 + arow_l;
    const bf16* aHiP = Ahi + arow * K + (tid & 1) * 16;
    const bf16* aLoP = Alo + arow * K + (tid & 1) * 16;
    const uint32_t aDst = smem_u32(db) + (uint32_t)(arow_l * ASTRIDE + (tid & 1) * 32);

    auto issueA = [&](int k0, int s) {
        const uint32_t so = (uint32_t)(s * STAGE);
        CP16(aDst + so,      aHiP + k0);
        CP16(aDst + so + 16, aHiP + k0 + 8);
        CP16(aDst + so + ALO_OFF,      aLoP + k0);
        CP16(aDst + so + ALO_OFF + 16, aLoP + k0 + 8);
    };

    // ---- B loader (fp32 LDG + split): thread -> k-row tid>>3, 16 n at (tid&7)*16 ----
    const int bkr  = tid >> 3;
    const int seg  = (tid & 7) * 16;          // local col 0..112
    const size_t eoff = (GATHER || AEXP) ? (size_t)e * K * Ntot : 0;
    const float* BP;
    if (DUAL) BP = (seg < 64 ? B0 + eoff + n0 + seg : B1 + eoff + n0 + seg - 64);
    else      BP = B0 + eoff + n0 + seg;
    BP += (size_t)bkr * Ntot;
    const uint32_t bOff = (uint32_t)(bkr * BSTRIDE + seg * 2);

    float4 pb[4];
    auto ldgB = [&](int k0) {
        const float4* p = (const float4*)(BP + (size_t)k0 * Ntot);
        pb[0] = p[0]; pb[1] = p[1]; pb[2] = p[2]; pb[3] = p[3];
    };
    auto stsB = [&](int s) {
        char* st = db + s * STAGE;
        uint2 h0, l0, h1, l1;
        split4(pb[0], h0, l0); split4(pb[1], h1, l1);
        *(uint4*)(st + BHI_OFF + bOff) = make_uint4(h0.x, h0.y, h1.x, h1.y);
        *(uint4*)(st + BLO_OFF + bOff) = make_uint4(l0.x, l0.y, l1.x, l1.y);
        split4(pb[2], h0, l0); split4(pb[3], h1, l1);
        *(uint4*)(st + BHI_OFF + bOff + 16) = make_uint4(h0.x, h0.y, h1.x, h1.y);
        *(uint4*)(st + BLO_OFF + bOff + 16) = make_uint4(l0.x, l0.y, l1.x, l1.y);
    };

    float acc[2][8][4];
    #pragma unroll
    for (int i = 0; i < 2; ++i)
        #pragma unroll
        for (int j = 0; j < 8; ++j)
            #pragma unroll
            for (int v = 0; v < 4; ++v) acc[i][j][v] = 0.f;

    const int grp = lane >> 3;
    const int gl  = lane & 7;
    const int a_row_off = (grp & 1) * 8 + gl;
    const int a_col_off = (grp >> 1) * 8;
    const int b_row_off = (grp & 1) * 8 + gl;
    const int b_col_off = (grp >> 1) * 8;

    const int C = K / 32;
    ldgB(0);
    issueA(0, 0);
    CP_COMMIT();

    for (int c = 0; c < C; ++c) {
        if (c + 1 < C) {
            issueA((c + 1) * 32, (c + 1) & 1);
            CP_COMMIT();
            CP_WAIT(1);
        } else {
            CP_WAIT(0);
        }
        stsB(c & 1);
        if (c + 1 < C) ldgB((c + 1) * 32);
        __syncthreads();

        const uint32_t base = smem_u32(db) + (uint32_t)((c & 1) * STAGE);
        #pragma unroll
        for (int ks = 0; ks < 32; ks += 16) {
            uint32_t ah[2][4], al[2][4];
            #pragma unroll
            for (int mi = 0; mi < 2; ++mi) {
                const uint32_t ra = base + (uint32_t)((wm * 32 + mi * 16 + a_row_off) * ASTRIDE + (ks + a_col_off) * 2);
                ldsm_x4(ah[mi], ra);
                ldsm_x4(al[mi], ra + ALO_OFF);
            }
            #pragma unroll
            for (int g = 0; g < 4; ++g) {
                uint32_t bh[4], bl[4];
                const uint32_t rb = base + (uint32_t)(BHI_OFF + (ks + b_row_off) * BSTRIDE + (wn * 64 + g * 16 + b_col_off) * 2);
                ldsm_x4_t(bh, rb);
                ldsm_x4_t(bl, rb + (BLO_OFF - BHI_OFF));
                #pragma unroll
                for (int mi = 0; mi < 2; ++mi) {
                    #pragma unroll
                    for (int half = 0; half < 2; ++half) {
                        const int nj = g * 2 + half;
                        const int p = half * 2;
                        mma16816(acc[mi][nj], ah[mi], bh[p], bh[p + 1]);
                        mma16816(acc[mi][nj], ah[mi], bl[p], bl[p + 1]);
                        mma16816(acc[mi][nj], al[mi], bh[p], bh[p + 1]);
                    }
                }
            }
        }
        __syncthreads();
    }

    // ---- epilogues ----
    if (EPI == 0) {
        float* exch = (float*)db;   // [128][72]
        if (wn == 1) {
            #pragma unroll
            for (int mi = 0; mi < 2; ++mi)
                #pragma unroll
                for (int nj = 0; nj < 8; ++nj) {
                    const int cl = nj * 8 + (lane & 3) * 2;
                    #pragma unroll
                    for (int h = 0; h < 2; ++h) {
                        const int rl = wm * 32 + mi * 16 + (lane >> 2) + h * 8;
                        exch[rl * 72 + cl]     = acc[mi][nj][h * 2];
                        exch[rl * 72 + cl + 1] = acc[mi][nj][h * 2 + 1];
                    }
                }
        }
        __syncthreads();
        if (wn == 0) {
            #pragma unroll
            for (int mi = 0; mi < 2; ++mi)
                #pragma unroll
                for (int h = 0; h < 2; ++h) {
                    const int rl = wm * 32 + mi * 16 + (lane >> 2) + h * 8;
                    const int r = m0 + rl;
                    if (GATHER && r >= cnt) continue;
                    const size_t row = (GATHER ? (size_t)e * T_TOKENS : 0) + r;
                    #pragma unroll
                    for (int nj = 0; nj < 8; ++nj) {
                        const int cl = nj * 8 + (lane & 3) * 2;
                        const float g0 = acc[mi][nj][h * 2];
                        const float g1 = acc[mi][nj][h * 2 + 1];
                        const float u0 = exch[rl * 72 + cl];
                        const float u1 = exch[rl * 72 + cl + 1];
                        const float a0 = (g0 / (1.f + expf(-g0))) * u0;
                        const float a1 = (g1 / (1.f + expf(-g1))) * u1;
                        uint32_t hi, lo; split2(a0, a1, hi, lo);
                        *(uint32_t*)(outHi + row * Ntot + n0 + cl) = hi;
                        *(uint32_t*)(outLo + row * Ntot + n0 + cl) = lo;
                    }
                }
        }
    } else {
        #pragma unroll
        for (int mi = 0; mi < 2; ++mi)
            #pragma unroll
            for (int h = 0; h < 2; ++h) {
                const int rl = wm * 32 + mi * 16 + (lane >> 2) + h * 8;
                const int r = m0 + rl;
                if (EPI == 1) {
                    if (r >= cnt) continue;
                    const int idx = e * T_TOKENS + r;
                    const float w = g_wt[idx];
                    float* orow = g_contrib + ((size_t)g_tok[idx] * 2 + g_slot[idx]) * H_DIM;
                    #pragma unroll
                    for (int nj = 0; nj < 8; ++nj) {
                        const int c = n0 + wn * 64 + nj * 8 + (lane & 3) * 2;
                        float2 o = {acc[mi][nj][h * 2] * w, acc[mi][nj][h * 2 + 1] * w};
                        *(float2*)(orow + c) = o;
                    }
                } else {
                    const float sg = g_sgate[r];
                    #pragma unroll
                    for (int nj = 0; nj < 8; ++nj) {
                        const int c = n0 + wn * 64 + nj * 8 + (lane & 3) * 2;
                        const float2 c0 = *(const float2*)(g_contrib + ((size_t)r * 2 + 0) * H_DIM + c);
                        const float2 c1 = *(const float2*)(g_contrib + ((size_t)r * 2 + 1) * H_DIM + c);
                        float2 o = {sg * acc[mi][nj][h * 2] + c0.x + c1.x,
                                    sg * acc[mi][nj][h * 2 + 1] + c0.y + c1.y};
                        *(float2*)(outF + (size_t)r * H_DIM + c) = o;
                    }
                }
            }
    }
}

// ---------------------------------------------------------------------------
extern "C" void kernel_launch(void* const* d_in, const int* in_sizes, int n_in,
                              void* d_out, int out_size)
{
    const float* hidden        = (const float*)d_in[0];
    const float* gate_w        = (const float*)d_in[1];
    const float* w_gate        = (const float*)d_in[2];
    const float* w_up          = (const float*)d_in[3];
    const float* w_down        = (const float*)d_in[4];
    const float* sw_gate       = (const float*)d_in[5];
    const float* sw_up         = (const float*)d_in[6];
    const float* sw_down       = (const float*)d_in[7];
    const float* shared_gate_w = (const float*)d_in[8];

    float* out        = (float*)d_out;
    float* out_logits = out + (size_t)T_TOKENS * H_DIM;

    bf16 *hidHi, *hidLo, *actHi, *actLo, *shHi, *shLo;
    cudaGetSymbolAddress((void**)&hidHi, g_hid_hi);  cudaGetSymbolAddress((void**)&hidLo, g_hid_lo);
    cudaGetSymbolAddress((void**)&actHi, g_act_hi);  cudaGetSymbolAddress((void**)&actLo, g_act_lo);
    cudaGetSymbolAddress((void**)&shHi, g_shact_hi); cudaGetSymbolAddress((void**)&shLo, g_shact_lo);

    cudaFuncSetAttribute(mma2_gemm<1,0,1,0>, cudaFuncAttributeMaxDynamicSharedMemorySize, SMEM_DYN);
    cudaFuncSetAttribute(mma2_gemm<0,1,0,1>, cudaFuncAttributeMaxDynamicSharedMemorySize, SMEM_DYN);
    cudaFuncSetAttribute(mma2_gemm<0,0,1,0>, cudaFuncAttributeMaxDynamicSharedMemorySize, SMEM_DYN);
    cudaFuncSetAttribute(mma2_gemm<0,0,0,2>, cudaFuncAttributeMaxDynamicSharedMemorySize, SMEM_DYN);

    zero_cnt_kernel<<<1, 32>>>();
    router_kernel<<<T_TOKENS, 256>>>(hidden, gate_w, shared_gate_w, out_logits);

    // hidden split only (8MB, ~4us)
    {
        int n4 = (int)((size_t)T_TOKENS * H_DIM / 4);
        split_kernel<<<(n4 + 255) / 256, 256>>>(hidden, hidHi, hidLo, n4);
    }

    // expert gate+up -> act hi/lo
    mma2_gemm<1,0,1,0><<<dim3(I_DIM / 64, T_TOKENS / 128, NE), 256, SMEM_DYN>>>(
        hidHi, hidLo, w_gate, w_up, actHi, actLo, nullptr, H_DIM, I_DIM);
    // expert down -> contrib scatter
    mma2_gemm<0,1,0,1><<<dim3(H_DIM / 128, T_TOKENS / 128, NE), 256, SMEM_DYN>>>(
        actHi, actLo, w_down, w_down, nullptr, nullptr, nullptr, I_DIM, H_DIM);
    // shared gate+up -> shact hi/lo
    mma2_gemm<0,0,1,0><<<dim3(SI_DIM / 64, T_TOKENS / 128, 1), 256, SMEM_DYN>>>(
        hidHi, hidLo, sw_gate, sw_up, shHi, shLo, nullptr, H_DIM, SI_DIM);
    // shared down + combine -> out
    mma2_gemm<0,0,0,2><<<dim3(H_DIM / 128, T_TOKENS / 128, 1), 256, SMEM_DYN>>>(
        shHi, shLo, sw_down, sw_down, nullptr, nullptr, out, SI_DIM, H_DIM);
}